// round 2
// baseline (speedup 1.0000x reference)
#include <cuda_runtime.h>
#include <cstdint>

// Problem dims (fixed by the dataset)
constexpr int Mdim  = 8192;   // global token rows (= 8 ranks * 1024)
constexpr int Ndim  = 4096;   // output features
constexpr int KL    = 512;    // per-rank K shard
constexpr int RANKS = 8;

// Tiling
#define BM 128
#define BN 128
#define BK 16
constexpr int KTILES = RANKS * (KL / BK);   // 256 k-tiles total

using u64 = unsigned long long;

// Packed fp32x2 FMA: d{lo,hi} += a{lo,hi} * b{lo,hi}.
// ptxas never emits this from C++ (SASS_QUICKREF: FFMA2 only via PTX) —
// it doubles fp32 FMA rate vs 3-reg FFMA (rt 2 -> 2 FLOPs/slot -> 128 FMA/cyc/SM).
__device__ __forceinline__ void ffma2(u64& d, u64 a, u64 b) {
    asm("fma.rn.f32x2 %0, %1, %2, %0;" : "+l"(d) : "l"(a), "l"(b));
}

// Stash one 128x16 A tile (duplicated {a,a} pairs) + 128x16 B tile into SMEM,
// transposing from global k-contiguous rows to k-outer SMEM layout.
__device__ __forceinline__ void stash_tile(
    float* __restrict__ asd,   // [BK][2*BM]
    float* __restrict__ bss,   // [BK][BN]
    int r0, int q,
    float4 a0, float4 a1, float4 b0, float4 b1)
{
    const float av0[4] = {a0.x, a0.y, a0.z, a0.w};
    const float av1[4] = {a1.x, a1.y, a1.z, a1.w};
    const float bv0[4] = {b0.x, b0.y, b0.z, b0.w};
    const float bv1[4] = {b1.x, b1.y, b1.z, b1.w};
#pragma unroll
    for (int i = 0; i < 4; i++) {
        const int k = q * 4 + i;
        float* arow = asd + k * (2 * BM);
        float* brow = bss + k * BN;
        arow[2 * r0]            = av0[i];
        arow[2 * r0 + 1]        = av0[i];
        arow[2 * (r0 + 64)]     = av1[i];
        arow[2 * (r0 + 64) + 1] = av1[i];
        brow[r0]      = bv0[i];
        brow[r0 + 64] = bv1[i];
    }
}

__global__ void __launch_bounds__(256)
gemm_rs_f32x2_kernel(const float* __restrict__ A,   // [8, 8192, 512]
                     const float* __restrict__ B,   // [8, 4096, 512]
                     float* __restrict__ C)         // [8192, 4096]
{
    // A duplicated pairs along M so the f32x2 "broadcast" operand comes
    // straight from SMEM (no pack MOVs on the fma pipe).
    __shared__ float AsD[2][BK][2 * BM];   // 32 KB
    __shared__ float Bs [2][BK][BN];       // 16 KB

    const int tid = threadIdx.x;
    const int tx  = tid & 15;          // N direction: 8 cols each
    const int ty  = tid >> 4;          // M direction: 8 rows each

    const int m0 = blockIdx.y * BM;
    const int n0 = blockIdx.x * BN;

    // Tile-load mapping: 128 rows x 16 floats = 512 float4; 2 per thread per matrix.
    const int r0 = tid >> 2;           // row 0..63 (second item at +64)
    const int q  = tid & 3;            // k-quad 0..3

    const float* A0 = A + (size_t)(m0 + r0) * KL + q * 4;
    const float* A1 = A0 + (size_t)64 * KL;
    const float* B0 = B + (size_t)(n0 + r0) * KL + q * 4;
    const float* B1 = B0 + (size_t)64 * KL;

    u64 acc[8][4];
#pragma unroll
    for (int i = 0; i < 8; i++)
#pragma unroll
        for (int j = 0; j < 4; j++) acc[i][j] = 0ull;   // bit pattern {0.f,0.f}

    // Prologue: load + stash tile 0 (src 0, k0 = 0)
    float4 pa0 = *(const float4*)(A0);
    float4 pa1 = *(const float4*)(A1);
    float4 pb0 = *(const float4*)(B0);
    float4 pb1 = *(const float4*)(B1);
    stash_tile(&AsD[0][0][0], &Bs[0][0][0], r0, q, pa0, pa1, pb0, pb1);
    __syncthreads();

    int buf = 0;
    for (int t = 0; t < KTILES; t++) {
        // Prefetch next tile into registers (hidden under ~1k cycles of FMA)
        if (t + 1 < KTILES) {
            const int nt = t + 1;
            const size_t offA = (size_t)(nt >> 5) * Mdim * KL + (size_t)(nt & 31) * BK;
            const size_t offB = (size_t)(nt >> 5) * Ndim * KL + (size_t)(nt & 31) * BK;
            pa0 = *(const float4*)(A0 + offA);
            pa1 = *(const float4*)(A1 + offA);
            pb0 = *(const float4*)(B0 + offB);
            pb1 = *(const float4*)(B1 + offB);
        }

        // Compute on current buffer: 16 k-steps x 32 ffma2 = 512 FFMA2/thread/tile
        {
            const float* asBase = &AsD[buf][0][0];
            const float* bsBase = &Bs[buf][0][0];
#pragma unroll
            for (int k = 0; k < BK; k++) {
                u64 a2[8], b2[4];
                const u64* ap = reinterpret_cast<const u64*>(asBase + k * (2 * BM) + 2 * (ty * 8));
                const u64* bp = reinterpret_cast<const u64*>(bsBase + k * BN + tx * 8);
#pragma unroll
                for (int i = 0; i < 8; i++) a2[i] = ap[i];
#pragma unroll
                for (int j = 0; j < 4; j++) b2[j] = bp[j];
#pragma unroll
                for (int i = 0; i < 8; i++)
#pragma unroll
                    for (int j = 0; j < 4; j++)
                        ffma2(acc[i][j], a2[i], b2[j]);
            }
        }

        // Stash next tile into the other buffer, one barrier per tile
        if (t + 1 < KTILES) {
            const int nb = buf ^ 1;
            stash_tile(&AsD[nb][0][0], &Bs[nb][0][0], r0, q, pa0, pa1, pb0, pb1);
            __syncthreads();
            buf = nb;
        }
    }

    // Epilogue: each thread owns C[m0+ty*8 .. +7][n0+tx*8 .. +7]
    float* crow = C + (size_t)(m0 + ty * 8) * Ndim + n0 + tx * 8;
#pragma unroll
    for (int i = 0; i < 8; i++) {
        u64* cp = reinterpret_cast<u64*>(crow + (size_t)i * Ndim);
#pragma unroll
        for (int j = 0; j < 4; j++) cp[j] = acc[i][j];
    }
}

extern "C" void kernel_launch(void* const* d_in, const int* in_sizes, int n_in,
                              void* d_out, int out_size)
{
    const float* a = (const float*)d_in[0];   // [8, 8192, 512] fp32
    const float* b = (const float*)d_in[1];   // [8, 4096, 512] fp32
    float* c = (float*)d_out;                 // [8, 1024, 4096] == [8192, 4096] fp32

    dim3 grid(Ndim / BN, Mdim / BM);          // (32, 64) = 2048 CTAs
    gemm_rs_f32x2_kernel<<<grid, 256>>>(a, b, c);
}

// round 4
// speedup vs baseline: 3.6079x; 3.6079x over previous
#include <cuda_runtime.h>
#include <cuda_bf16.h>
#include <cstdint>

using u32 = uint32_t;

// ---------------- problem dims ----------------
constexpr int Mdim = 8192, Ndim = 4096, KL = 512, RANKS = 8;
constexpr int K3 = RANKS * KL * 3;            // 12288: split-bf16 3-term packed K

// ---------------- GEMM tiling ----------------
constexpr int BM = 256;                        // M per CTA
constexpr int BN = 128;                        // N per CTA
constexpr int BKB = 64;                        // bf16 k per SMEM stage (128B rows)
constexpr int NT = K3 / BKB;                   // 192 k-tiles
constexpr int THREADS = 512;                   // 16 warps: 4(m) x 4(n)

constexpr int A_BYTES = BM * 128;              // 32 KB
constexpr int B_BYTES = BN * 128;              // 16 KB
constexpr int STAGE_BYTES = A_BYTES + B_BYTES; // 48 KB
constexpr int STAGES = 3;
constexpr int SMEM_TOTAL = STAGES * STAGE_BYTES;   // 147456

// ---------------- scratch (device globals = sanctioned scratch) ----------------
__device__ __nv_bfloat16 g_A3[(size_t)Mdim * K3];   // 201 MB
__device__ __nv_bfloat16 g_B3[(size_t)Ndim * K3];   // 100 MB

// ---------------- PTX helpers (all arch-portable: sm_80+) ----------------
__device__ __forceinline__ u32 smem_u32(const void* p) {
    u32 r;
    asm("{ .reg .u64 t; cvta.to.shared.u64 t, %1; cvt.u32.u64 %0, t; }"
        : "=r"(r) : "l"(p));
    return r;
}
__device__ __forceinline__ u32 swz128(u32 off) { return off ^ ((off >> 3) & 0x70); }

__device__ __forceinline__ void cp_async16(u32 saddr, const void* gaddr) {
    asm volatile("cp.async.cg.shared.global [%0], [%1], 16;"
                 :: "r"(saddr), "l"(gaddr) : "memory");
}
__device__ __forceinline__ void cp_commit() {
    asm volatile("cp.async.commit_group;" ::: "memory");
}
__device__ __forceinline__ void cp_wait2() {
    asm volatile("cp.async.wait_group 2;" ::: "memory");
}

__device__ __forceinline__ void ldsm_x4(u32& r0, u32& r1, u32& r2, u32& r3, u32 a) {
    asm volatile("ldmatrix.sync.aligned.m8n8.x4.shared.b16 {%0,%1,%2,%3}, [%4];"
                 : "=r"(r0), "=r"(r1), "=r"(r2), "=r"(r3) : "r"(a));
}
__device__ __forceinline__ void ldsm_x2(u32& r0, u32& r1, u32 a) {
    asm volatile("ldmatrix.sync.aligned.m8n8.x2.shared.b16 {%0,%1}, [%2];"
                 : "=r"(r0), "=r"(r1) : "r"(a));
}
__device__ __forceinline__ void hmma_bf16(float* c, const u32* a, const u32* b) {
    asm volatile(
        "mma.sync.aligned.m16n8k16.row.col.f32.bf16.bf16.f32 "
        "{%0,%1,%2,%3}, {%4,%5,%6,%7}, {%8,%9}, {%0,%1,%2,%3};"
        : "+f"(c[0]), "+f"(c[1]), "+f"(c[2]), "+f"(c[3])
        : "r"(a[0]), "r"(a[1]), "r"(a[2]), "r"(a[3]), "r"(b[0]), "r"(b[1]));
}

// ---------------- conversion: fp32 -> split-bf16 triplets ----------------
// A3[m][(src*KL+k)*3 + {0,1,2}] = {hi, hi, lo}(a[src][m][k])
// B3[n][(src*KL+k)*3 + {0,1,2}] = {hi, lo, hi}(b[src][n][k])
// => sum = hi*hi + hi*lo + lo*hi  (drops lo*lo ~ 2^-18 relative)
__global__ void __launch_bounds__(256)
convert_kernel(const float* __restrict__ a, const float* __restrict__ b)
{
    constexpr size_t ACH = (size_t)RANKS * Mdim * KL / 8;   // 4,194,304
    constexpr size_t BCH = (size_t)RANKS * Ndim * KL / 8;   // 2,097,152
    size_t id = (size_t)blockIdx.x * 256 + threadIdx.x;
    if (id >= ACH + BCH) return;

    bool isA = id < ACH;
    size_t cid = isA ? id : id - ACH;

    size_t src_row = cid >> 6;            // 64 chunks of 8 floats per (src,row)
    int k0 = (int)(cid & 63) * 8;
    int srk, row;
    if (isA) { srk = (int)(src_row / Mdim); row = (int)(src_row % Mdim); }
    else     { srk = (int)(src_row / Ndim); row = (int)(src_row % Ndim); }

    const float* src = (isA ? a : b) + cid * 8;
    __nv_bfloat16* dst = (isA ? g_A3 : g_B3)
        + (size_t)row * K3 + (size_t)(srk * KL + k0) * 3;

    float4 f0 = ((const float4*)src)[0];
    float4 f1 = ((const float4*)src)[1];
    float xs[8] = {f0.x, f0.y, f0.z, f0.w, f1.x, f1.y, f1.z, f1.w};

    __align__(16) __nv_bfloat16 ov[24];
#pragma unroll
    for (int i = 0; i < 8; i++) {
        float x = xs[i];
        __nv_bfloat16 h = __float2bfloat16(x);
        __nv_bfloat16 l = __float2bfloat16(x - __bfloat162float(h));
        if (isA) { ov[3*i] = h; ov[3*i+1] = h; ov[3*i+2] = l; }
        else     { ov[3*i] = h; ov[3*i+1] = l; ov[3*i+2] = h; }
    }
    uint4* d4 = (uint4*)dst;
    const uint4* s4 = (const uint4*)ov;
    d4[0] = s4[0]; d4[1] = s4[1]; d4[2] = s4[2];
}

// ---------------- HMMA GEMM: C[8192,4096] = A3 @ B3^T ----------------
__global__ void __launch_bounds__(THREADS, 1)
gemm_mma_kernel(float* __restrict__ C)
{
    extern __shared__ __align__(1024) char smem[];
    const u32 sbase = smem_u32(smem);
    const int tid = threadIdx.x;
    const int lane = tid & 31;
    const int w = tid >> 5;            // 16 warps
    const int wm = w >> 2;             // 0..3 : warp row  (64 M each)
    const int wn = w & 3;              // 0..3 : warp col  (32 N each)

    const int m0 = blockIdx.y * BM;
    const int n0 = blockIdx.x * BN;

    // ---- cp.async tile-load mapping: 3072 x 16B chunks, 6 per thread ----
    u32 soff[6];
    const __nv_bfloat16* gp[6];
#pragma unroll
    for (int i = 0; i < 6; i++) {
        int id = tid + i * THREADS;
        if (id < 2048) {                    // A: 256 rows x 8 chunks
            int row = id >> 3, c = id & 7;
            soff[i] = swz128(row * 128 + c * 16);
            gp[i] = g_A3 + (size_t)(m0 + row) * K3 + c * 8;
        } else {                            // B: 128 rows x 8 chunks
            int j = id - 2048;
            int row = j >> 3, c = j & 7;
            soff[i] = A_BYTES + swz128(row * 128 + c * 16);
            gp[i] = g_B3 + (size_t)(n0 + row) * K3 + c * 8;
        }
    }

    // ---- ldmatrix address precomputation ----
    // swz128(row*128 + col2) = row*128 + (col2 ^ ((row&7)*16)) for col2 < 128.
    // A (x4): lane -> mat = lane/8; row = base + (mat&1)*8 + lane%8; col += (mat>>1)*8
    const int a_xor = (lane & 7) * 16;
    const u32 a_colt = ((lane >> 4) & 1) * 16;              // byte offset of k-half
    u32 aPre[4];
#pragma unroll
    for (int mb = 0; mb < 4; mb++) {
        int row = wm * 64 + mb * 16 + (((lane >> 3) & 1) << 3) + (lane & 7);
        aPre[mb] = (u32)row * 128;
    }
    // B (x2): lanes 0-15 used; mat = (lane>>3)&1 selects k-half
    const u32 b_colt = ((lane >> 3) & 1) * 16;
    u32 bPre[4];
#pragma unroll
    for (int nb = 0; nb < 4; nb++) {
        int row = wn * 32 + nb * 8 + (lane & 7);
        bPre[nb] = (u32)row * 128;
    }

    float acc[4][4][4];
#pragma unroll
    for (int i = 0; i < 4; i++)
#pragma unroll
        for (int j = 0; j < 4; j++)
#pragma unroll
            for (int q = 0; q < 4; q++) acc[i][j][q] = 0.f;

    // ---- prologue: stage tiles 0 and 1 ----
#pragma unroll
    for (int p = 0; p < 2; p++) {
        u32 sb = sbase + p * STAGE_BYTES;
#pragma unroll
        for (int i = 0; i < 6; i++)
            cp_async16(sb + soff[i], gp[i] + (size_t)p * BKB);
        cp_commit();
    }

    // ---- main loop ----
    for (int t = 0; t < NT; t++) {
        if (t + 2 < NT) {
            const u32 sb = sbase + ((t + 2) % 3) * STAGE_BYTES;
#pragma unroll
            for (int i = 0; i < 6; i++)
                cp_async16(sb + soff[i], gp[i] + (size_t)(t + 2) * BKB);
        }
        cp_commit();
        cp_wait2();                 // tile t's data resident
        __syncthreads();

        const u32 sA = sbase + (t % 3) * STAGE_BYTES;
        const u32 sB = sA + A_BYTES;

#pragma unroll
        for (int ks = 0; ks < 4; ks++) {
            const u32 kbyte = (u32)ks * 32;
            u32 af[4][4];
#pragma unroll
            for (int mb = 0; mb < 4; mb++)
                ldsm_x4(af[mb][0], af[mb][1], af[mb][2], af[mb][3],
                        sA + aPre[mb] + ((kbyte + a_colt) ^ a_xor));
            u32 bf[4][2];
#pragma unroll
            for (int nb = 0; nb < 4; nb++)
                ldsm_x2(bf[nb][0], bf[nb][1],
                        sB + bPre[nb] + ((kbyte + b_colt) ^ a_xor));
#pragma unroll
            for (int mb = 0; mb < 4; mb++)
#pragma unroll
                for (int nb = 0; nb < 4; nb++)
                    hmma_bf16(acc[mb][nb], af[mb], bf[nb]);
        }
        __syncthreads();            // compute done before stage refill
    }

    // ---- epilogue ----
    // c-frag: {c0,c1} at (row lane/4,   col (lane%4)*2), {c2,c3} at row+8
    const int er = lane >> 2;
    const int ec = (lane & 3) * 2;
#pragma unroll
    for (int mb = 0; mb < 4; mb++) {
#pragma unroll
        for (int nb = 0; nb < 4; nb++) {
            float* base = C + (size_t)(m0 + wm * 64 + mb * 16 + er) * Ndim
                            + (n0 + wn * 32 + nb * 8 + ec);
            float2 v0 = {acc[mb][nb][0], acc[mb][nb][1]};
            float2 v1 = {acc[mb][nb][2], acc[mb][nb][3]};
            *(float2*)base = v0;
            *(float2*)(base + (size_t)8 * Ndim) = v1;
        }
    }
}

// ---------------- launch ----------------
extern "C" void kernel_launch(void* const* d_in, const int* in_sizes, int n_in,
                              void* d_out, int out_size)
{
    const float* a = (const float*)d_in[0];   // [8, 8192, 512] fp32
    const float* b = (const float*)d_in[1];   // [8, 4096, 512] fp32
    float* c = (float*)d_out;                 // [8192, 4096] fp32

    constexpr size_t TOTAL_CHUNKS =
        ((size_t)RANKS * Mdim * KL + (size_t)RANKS * Ndim * KL) / 8;  // 6,291,456
    convert_kernel<<<(unsigned)(TOTAL_CHUNKS / 256), 256>>>(a, b);

    cudaFuncSetAttribute(gemm_mma_kernel,
                         cudaFuncAttributeMaxDynamicSharedMemorySize, SMEM_TOTAL);
    dim3 grid(Ndim / BN, Mdim / BM);          // (32, 32) = 1024 CTAs
    gemm_mma_kernel<<<grid, THREADS, SMEM_TOTAL>>>(c);
}